// round 7
// baseline (speedup 1.0000x reference)
#include <cuda_runtime.h>
#include <cuda_bf16.h>
#include <math.h>

#define D        32
#define HALF     16
#define DP1      33       // D+1
#define MAX_NR   1024
#define MAX_NE   1000000

#define TPB      256

// Per-relation tables (all rows 128B so every row is one cache line):
//   g_cs[r*16+j] = (cv*cos(rot_j), cv*sin(rot_j))      j = 0..15
//   g_w [r*32+l] = sinh(vn)/vn * 0.1*trans_l            l = 0..31
//   g_b [r]      = (cv*sinh(rap), cosh(rap))
__device__ __align__(128) float2 g_cs[MAX_NR * 16];
__device__ __align__(128) float  g_w [MAX_NR * 32];
__device__ float2 g_b[MAX_NR];
// Per-entity packed (x0, bias)
__device__ float2 g_sc[MAX_NE];

// ---------------------------------------------------------------------------
// Merged prelude: every thread packs one entity's (x0,bias); the first NR
// warps additionally build their relation's table (warp-cooperative).
// NR*32 << NE so relation warps are fully populated — shfl masks are safe.
// ---------------------------------------------------------------------------
__global__ void prelude(const float* __restrict__ ent,
                        const float* __restrict__ bias,
                        const float* __restrict__ boost,
                        const float* __restrict__ rot,
                        const float* __restrict__ trans,
                        int NE, int NR) {
    const unsigned FULL = 0xFFFFFFFFu;
    int g    = blockIdx.x * blockDim.x + threadIdx.x;
    int lane = threadIdx.x & 31;
    int wid  = g >> 5;

    if (g < NE)
        g_sc[g] = make_float2(__ldg(ent + g * DP1), __ldg(bias + g));

    if (wid < NR) {
        int r = wid;
        // v = 0.1*trans; vn = sqrt(max(|v|^2,1e-6)); w = sinh(vn)/vn * v
        float v  = 0.1f * trans[r * D + lane];
        float sq = v * v;
        #pragma unroll
        for (int off = 16; off; off >>= 1)
            sq += __shfl_xor_sync(FULL, sq, off);
        float vn  = sqrtf(fmaxf(sq, 1e-6f));
        float cv  = coshf(vn);
        float svn = sinhf(vn) / vn;
        g_w[r * D + lane] = svn * v;

        if (lane < HALF) {
            float s, c;
            sincosf(rot[r * D + lane], &s, &c);
            g_cs[r * HALF + lane] = make_float2(cv * c, cv * s);
        }
        if (lane == 0) {
            float rap = fminf(fmaxf(boost[r * D], -2.0f), 2.0f);
            g_b[r] = make_float2(cv * sinhf(rap), coshf(rap));
        }
    }
}

// ---------------------------------------------------------------------------
// Main: full-warp cooperative, 1 sample/iter, 32 iters. Lane l owns dim l.
// Entity row read = one 32-lane scalar LDG (bytes 4..131, ~2 lines).
// Relation reads: 1-line (c,s) row + 1-line w row + broadcast boost pair.
// Dual reduction: lower half reduces ss2, upper half dt (7 shfl total).
// ---------------------------------------------------------------------------
__global__ __launch_bounds__(TPB, 6) void score32(
        const int*   __restrict__ heads,
        const int*   __restrict__ rels,
        const int*   __restrict__ tails,
        const float* __restrict__ ent,    // [NE,33]
        float*       __restrict__ out,
        int B) {

    const unsigned FULL = 0xFFFFFFFFu;
    const int lane = threadIdx.x & 31;
    const int wid  = (blockIdx.x * TPB + threadIdx.x) >> 5;
    const int i    = wid * 32 + lane;
    const int ic   = min(i, B - 1);
    const int l16  = lane & 15;
    const bool lo  = (lane < HALF);
    const float sgn = lo ? -1.0f : 1.0f;   // rotation sign per half

    // Coalesced idx loads; random per-own-sample (x0,bias) gathers.
    const int hi_v = heads[ic];
    const int ri_v = rels [ic];
    const int ti_v = tails[ic];
    float2 sh = g_sc[hi_v];                // (h0, bias_h)
    float2 st = g_sc[ti_v];                // (t0, bias_t)
    const float bsum   = sh.y + st.y;
    const float t0_own = st.x;
    const float h0_own = sh.x;

    float kss2 = 0.0f, kdt = 0.0f;

    #pragma unroll 8
    for (int it = 0; it < 32; ++it) {
        int   hs  = __shfl_sync(FULL, hi_v,   it);
        int   ts  = __shfl_sync(FULL, ti_v,   it);
        int   rs  = __shfl_sync(FULL, ri_v,   it);
        float h0s = __shfl_sync(FULL, h0_own, it);

        // Entity rows: one 32-lane scalar LDG each (~2 lines per row).
        float own = __ldcg(ent + hs * DP1 + 1 + lane);   // h_sp[lane]
        float tsp = __ldcg(ent + ts * DP1 + 1 + lane);   // t_sp[lane]

        float2 cs = __ldg(&g_cs[rs * HALF + l16]);       // 1 line, broadcast-shared
        float  w  = __ldg(&g_w [rs * D + lane]);         // 1 line
        float2 bb = __ldg(&g_b [rs]);                    // broadcast (cv*s0, c0)

        // Rotation: partner dim = lane^16.
        float p = __shfl_xor_sync(FULL, own, HALF);
        float q = fmaf(sgn * cs.y, p, cs.x * own);       // cv * rotated[lane]
        // res = q + w, except dim 0 gets the boost mix.
        float res = (lane == 0) ? fmaf(bb.y, q, fmaf(bb.x, h0s, w))
                                : (q + w);

        float ss2 = res * res;
        float dt  = res * tsp;

        // Dual reduction: 7 shfl. Lower half sums ss2, upper half sums dt.
        float s2 = ss2 + __shfl_xor_sync(FULL, ss2, HALF);
        float d2 = dt  + __shfl_xor_sync(FULL, dt,  HALF);
        float z  = lo ? s2 : d2;
        #pragma unroll
        for (int off = 1; off < HALF; off <<= 1)
            z += __shfl_xor_sync(FULL, z, off);
        float zz = __shfl_xor_sync(FULL, z, HALF);
        float ss2_tot = lo ? z  : zz;
        float dt_tot  = lo ? zz : z;

        // Lane `it` owns sample `it` of this warp.
        bool keep = (lane == it);
        kss2 = keep ? ss2_tot : kss2;
        kdt  = keep ? dt_tot  : kdt;
    }

    // Epilogue once per lane on its own sample.
    float ht0   = sqrtf(1.0f + kss2);        // _project time component
    float inner = kdt - ht0 * t0_own;
    float icl   = fmaxf(-inner, 1.0f + 1e-6f);
    float dd    = acoshf(icl);
    if (i < B)
        out[i] = fmaf(-dd, dd, bsum);        // coalesced store
}

// ---------------------------------------------------------------------------
extern "C" void kernel_launch(void* const* d_in, const int* in_sizes, int n_in,
                              void* d_out, int out_size) {
    const int*   heads = (const int*)  d_in[0];
    const int*   rels  = (const int*)  d_in[1];
    const int*   tails = (const int*)  d_in[2];
    const float* ent   = (const float*)d_in[3];
    const float* bw    = (const float*)d_in[4];
    const float* rw    = (const float*)d_in[5];
    const float* tw    = (const float*)d_in[6];
    const float* bias  = (const float*)d_in[7];
    float* out = (float*)d_out;

    int B  = in_sizes[0];
    int NR = in_sizes[4] / D;
    int NE = in_sizes[3] / DP1;

    // Merged prelude: grid covers NE threads; first NR warps also build rels.
    int pgrid = (NE + TPB - 1) / TPB;
    int minw  = (NR * 32 + TPB - 1) / TPB;
    if (pgrid < minw) pgrid = minw;
    prelude<<<pgrid, TPB>>>(ent, bias, bw, rw, tw, NE, NR);

    int nwarps = (B + 31) / 32;
    int grid   = (nwarps * 32 + TPB - 1) / TPB;
    score32<<<grid, TPB>>>(heads, rels, tails, ent, out, B);
}

// round 8
// speedup vs baseline: 1.3700x; 1.3700x over previous
#include <cuda_runtime.h>
#include <cuda_bf16.h>
#include <math.h>

#define D        32
#define HALF     16
#define DP1      33       // D+1
#define RSTRIDE4 16       // float4s per relation row (256 B)
#define MAX_NR   1024
#define MAX_NE   1000000

#define TPB      256

// Per-relation table, one float4 per lane l16=0..15:
//   R4[l16] = (C, S, w1, w2) = (cv*c[l16], cv*s[l16], w[l16], w[l16+16])
__device__ __align__(256) float4 g_relTab[MAX_NR * RSTRIDE4];
// Per-relation boost scalars: (cv*s0, c0, w[0], 0)
__device__ float4 g_boost[MAX_NR];
// Per-entity packed (x0, bias)
__device__ float2 g_sc[MAX_NE];

// ---------------------------------------------------------------------------
// Merged prelude: every thread packs one entity's (x0,bias); the first NR
// warps additionally build their relation's table (warp-cooperative).
// ---------------------------------------------------------------------------
__global__ void prelude(const float* __restrict__ ent,
                        const float* __restrict__ bias,
                        const float* __restrict__ boost,
                        const float* __restrict__ rot,
                        const float* __restrict__ trans,
                        int NE, int NR) {
    const unsigned FULL = 0xFFFFFFFFu;
    int g    = blockIdx.x * blockDim.x + threadIdx.x;
    int lane = threadIdx.x & 31;
    int wid  = g >> 5;

    if (g < NE)
        g_sc[g] = make_float2(__ldg(ent + g * DP1), __ldg(bias + g));

    if (wid < NR) {
        int r = wid;
        // v = 0.1*trans; vn = sqrt(max(|v|^2,1e-6)); w = sinh(vn)/vn * v
        float v  = 0.1f * trans[r * D + lane];
        float sq = v * v;
        #pragma unroll
        for (int off = 16; off; off >>= 1)
            sq += __shfl_xor_sync(FULL, sq, off);
        float vn  = sqrtf(fmaxf(sq, 1e-6f));
        float cv  = coshf(vn);
        float svn = sinhf(vn) / vn;
        float w   = svn * v;

        float whi = __shfl_down_sync(FULL, w, 16);   // lane<16: w[lane+16]

        float s = 0.0f, c = 0.0f;
        float rv = (lane < HALF) ? rot[r * D + lane] : 0.0f;
        sincosf(rv, &s, &c);

        if (lane < HALF)
            g_relTab[r * RSTRIDE4 + lane] = make_float4(cv * c, cv * s, w, whi);

        if (lane == 0) {
            float rap = fminf(fmaxf(boost[r * D], -2.0f), 2.0f);
            g_boost[r] = make_float4(cv * sinhf(rap), coshf(rap), w, 0.0f);
        }
    }
}

// ---------------------------------------------------------------------------
// Main: 16-lane groups, 2 samples/iter, 16 iters/warp (R6 structure).
// Lane l16 owns dims (l16, l16+16) of the group's sample. One float4/lane of
// relation data; boost via shuffled per-sample scalars; 6-shfl dual reduction.
// ---------------------------------------------------------------------------
__global__ __launch_bounds__(TPB, 7) void score16(
        const int*   __restrict__ heads,
        const int*   __restrict__ rels,
        const int*   __restrict__ tails,
        const float* __restrict__ ent,    // [NE,33]
        float*       __restrict__ out,
        int B) {

    const unsigned FULL = 0xFFFFFFFFu;
    const int lane = threadIdx.x & 31;
    const int wid  = (blockIdx.x * TPB + threadIdx.x) >> 5;
    const int i    = wid * 32 + lane;
    const int ic   = min(i, B - 1);
    const int l16  = lane & 15;
    const int gsel = lane & 16;
    const bool hi8 = (l16 & 8) != 0;

    // Coalesced idx loads; random per-own-sample gathers.
    const int hi_v = heads[ic];
    const int ri_v = rels [ic];
    const int ti_v = tails[ic];

    float2 sh = g_sc[hi_v];                 // (h0, bias_h)
    float2 st = g_sc[ti_v];                 // (t0, bias_t)
    float4 b4 = __ldg(&g_boost[ri_v]);      // (cv*s0, c0, w0, 0)
    const float bsum   = sh.y + st.y;
    const float t0_own = st.x;
    const float c0_own = b4.y;
    const float bterm  = fmaf(b4.x, sh.x, b4.z);   // cv*s0*h0 + w[0]

    float kss2 = 0.0f, kdt = 0.0f;

    #pragma unroll 4
    for (int it = 0; it < 16; ++it) {
        const int src = gsel | it;          // sample this half-warp processes
        int   hs   = __shfl_sync(FULL, hi_v,  src);
        int   ts   = __shfl_sync(FULL, ti_v,  src);
        int   rs   = __shfl_sync(FULL, ri_v,  src);
        float bts  = __shfl_sync(FULL, bterm, src);
        float c0s  = __shfl_sync(FULL, c0_own, src);

        const float* hr = ent + hs * DP1;
        const float* tr = ent + ts * DP1;
        float a  = __ldcg(hr + 1  + l16);   // h_sp[l16]
        float b  = __ldcg(hr + 17 + l16);   // h_sp[l16+16]
        float ta = __ldcg(tr + 1  + l16);
        float tb = __ldcg(tr + 17 + l16);

        float4 cw = __ldg(&g_relTab[rs * RSTRIDE4 + l16]);  // (C,S,w1,w2)

        float r1   = cw.x * a - cw.y * b;                   // cv * rotated[l16]
        float res1 = (l16 == 0) ? fmaf(c0s, r1, bts)        // boost + trans dim0
                                : (r1 + cw.z);
        float res2 = fmaf(cw.y, a, fmaf(cw.x, b, cw.w));    // cv*rot[l16+16]+w2

        float ss2 = fmaf(res1, res1, res2 * res2);
        float dt  = fmaf(res1, ta,   res2 * tb);

        // 6-shfl dual reduction within each 16-lane half:
        //   fold offset 8 for both vars, pack (ss2->lanes l16<8, dt->l16>=8),
        //   reduce combined over {1,2,4}, final xor(8) swap shares both.
        float u = ss2 + __shfl_xor_sync(FULL, ss2, 8);
        float v = dt  + __shfl_xor_sync(FULL, dt,  8);
        float z = hi8 ? v : u;
        #pragma unroll
        for (int off = 1; off < 8; off <<= 1)
            z += __shfl_xor_sync(FULL, z, off);
        float zz = __shfl_xor_sync(FULL, z, 8);
        float ss2_tot = hi8 ? zz : z;
        float dt_tot  = hi8 ? z  : zz;

        bool keep = (l16 == it);            // lane src owns sample src
        kss2 = keep ? ss2_tot : kss2;
        kdt  = keep ? dt_tot  : kdt;
    }

    // Epilogue once per lane on its own sample.
    float ht0   = sqrtf(1.0f + kss2);       // _project time component
    float inner = kdt - ht0 * t0_own;
    float icl   = fmaxf(-inner, 1.0f + 1e-6f);
    float dd    = acoshf(icl);
    if (i < B)
        out[i] = fmaf(-dd, dd, bsum);       // coalesced store
}

// ---------------------------------------------------------------------------
extern "C" void kernel_launch(void* const* d_in, const int* in_sizes, int n_in,
                              void* d_out, int out_size) {
    const int*   heads = (const int*)  d_in[0];
    const int*   rels  = (const int*)  d_in[1];
    const int*   tails = (const int*)  d_in[2];
    const float* ent   = (const float*)d_in[3];
    const float* bw    = (const float*)d_in[4];
    const float* rw    = (const float*)d_in[5];
    const float* tw    = (const float*)d_in[6];
    const float* bias  = (const float*)d_in[7];
    float* out = (float*)d_out;

    int B  = in_sizes[0];
    int NR = in_sizes[4] / D;
    int NE = in_sizes[3] / DP1;

    int pgrid = (NE + TPB - 1) / TPB;
    int minw  = (NR * 32 + TPB - 1) / TPB;
    if (pgrid < minw) pgrid = minw;
    prelude<<<pgrid, TPB>>>(ent, bias, bw, rw, tw, NE, NR);

    int nwarps = (B + 31) / 32;
    int grid   = (nwarps * 32 + TPB - 1) / TPB;
    score16<<<grid, TPB>>>(heads, rels, tails, ent, out, B);
}